// round 2
// baseline (speedup 1.0000x reference)
#include <cuda_runtime.h>
#include <math.h>

#define N_TOK 2048
#define D_DIM 1024
#define H_DIM 4096
#define E_NUM 8
#define R_DIM 16
#define LSCALE 2.0f   // lora_alpha / lora_r = 32/16

// ---------------- scratch (device globals; no allocation allowed) ----------------
__device__ float g_common[N_TOK * H_DIM];          // x @ W1^T             (33.5 MB)
__device__ float g_act[N_TOK * 2 * H_DIM];         // silu(fc1) per slot   (67 MB)
__device__ float g_base2[N_TOK * 2 * D_DIM];       // a @ W2^T per slot    (16.8 MB)
__device__ float g_t1[N_TOK * 2 * R_DIM];          // x @ A1[e]^T
__device__ float g_t2[N_TOK * 2 * R_DIM];          // a @ A2[e]^T
__device__ int   g_sel[N_TOK * 2];
__device__ float g_wt[N_TOK * 2];

// ---------------- router: logits -> softmax -> top2 -> renormalize ----------------
// softmax-then-top2-then-renorm == softmax over the top-2 logits.
__global__ void router_kernel(const float* __restrict__ x, const float* __restrict__ gate) {
    int t = blockIdx.x;
    int warp = threadIdx.x >> 5, lane = threadIdx.x & 31;
    __shared__ float logits[E_NUM];
    const float4* xr = (const float4*)(x + (size_t)t * D_DIM);
    const float4* gr = (const float4*)(gate + (size_t)warp * D_DIM);
    float s = 0.f;
    for (int i = lane; i < D_DIM / 4; i += 32) {
        float4 a = xr[i], b = gr[i];
        s += a.x * b.x + a.y * b.y + a.z * b.z + a.w * b.w;
    }
    #pragma unroll
    for (int o = 16; o; o >>= 1) s += __shfl_xor_sync(0xffffffffu, s, o);
    if (lane == 0) logits[warp] = s;
    __syncthreads();
    if (threadIdx.x == 0) {
        float best = -1e30f; int i0 = 0;
        #pragma unroll
        for (int e = 0; e < E_NUM; e++) if (logits[e] > best) { best = logits[e]; i0 = e; }
        float best2 = -1e30f; int i1 = 0;
        #pragma unroll
        for (int e = 0; e < E_NUM; e++) if (e != i0 && logits[e] > best2) { best2 = logits[e]; i1 = e; }
        float p1 = expf(best2 - best);
        float inv = 1.f / (1.f + p1);
        g_sel[t * 2 + 0] = i0; g_sel[t * 2 + 1] = i1;
        g_wt[t * 2 + 0] = inv; g_wt[t * 2 + 1] = p1 * inv;
    }
}

// ---------------- fp32 tiled GEMM:  C[M,N] = A[M,K] @ B[N,K]^T  ----------------
// 128x128 tile, BK=16, 256 threads, 8x8 register blocking.
// M,N multiples of 128; K multiple of 16 (true for all call sites).
__global__ __launch_bounds__(256, 2)
void gemm_nt_kernel(const float* __restrict__ A, const float* __restrict__ B,
                    float* __restrict__ C, int M, int N, int K) {
    const int BM = 128, BN = 128, BK = 16;
    __shared__ float As[BK][BM];
    __shared__ float Bs[BK][BN];
    int bm = blockIdx.y * BM, bn = blockIdx.x * BN;
    int tid = threadIdx.x;
    int tx = tid & 15, ty = tid >> 4;

    float acc[8][8];
    #pragma unroll
    for (int i = 0; i < 8; i++)
        #pragma unroll
        for (int j = 0; j < 8; j++) acc[i][j] = 0.f;

    for (int k0 = 0; k0 < K; k0 += BK) {
        #pragma unroll
        for (int l = 0; l < 2; l++) {
            int i = tid * 2 + l;          // 0..511 float4 loads
            int row = i >> 2;
            int kq = i & 3;
            float4 v = *(const float4*)(A + (size_t)(bm + row) * K + k0 + kq * 4);
            As[kq * 4 + 0][row] = v.x;
            As[kq * 4 + 1][row] = v.y;
            As[kq * 4 + 2][row] = v.z;
            As[kq * 4 + 3][row] = v.w;
        }
        #pragma unroll
        for (int l = 0; l < 2; l++) {
            int i = tid * 2 + l;
            int row = i >> 2;
            int kq = i & 3;
            float4 v = *(const float4*)(B + (size_t)(bn + row) * K + k0 + kq * 4);
            Bs[kq * 4 + 0][row] = v.x;
            Bs[kq * 4 + 1][row] = v.y;
            Bs[kq * 4 + 2][row] = v.z;
            Bs[kq * 4 + 3][row] = v.w;
        }
        __syncthreads();
        #pragma unroll
        for (int kk = 0; kk < BK; kk++) {
            float ar[8], br[8];
            #pragma unroll
            for (int i = 0; i < 4; i++) {
                ((float4*)ar)[0] = *(const float4*)&As[kk][ty * 8];
                ((float4*)ar)[1] = *(const float4*)&As[kk][ty * 8 + 4];
                ((float4*)br)[0] = *(const float4*)&Bs[kk][tx * 8];
                ((float4*)br)[1] = *(const float4*)&Bs[kk][tx * 8 + 4];
                break;
            }
            #pragma unroll
            for (int i = 0; i < 8; i++)
                #pragma unroll
                for (int j = 0; j < 8; j++)
                    acc[i][j] += ar[i] * br[j];
        }
        __syncthreads();
    }
    #pragma unroll
    for (int i = 0; i < 8; i++) {
        int row = bm + ty * 8 + i;
        float4* cr = (float4*)(C + (size_t)row * N + bn + tx * 8);
        cr[0] = make_float4(acc[i][0], acc[i][1], acc[i][2], acc[i][3]);
        cr[1] = make_float4(acc[i][4], acc[i][5], acc[i][6], acc[i][7]);
    }
}

// ---------------- rank-16 down-projection: T[p][r] = xrow(p) . Amat[e(p)][r][:] ----------------
// half_index=1: xrow = X + (p/2)*K (token row);  half_index=0: xrow = X + p*K (act row)
__global__ void lora_in_kernel(const float* __restrict__ X, const float* __restrict__ Amat,
                               float* __restrict__ Tout, int K, int half_index) {
    int p = blockIdx.x;
    int e = g_sel[p];
    const float4* xr = (const float4*)(X + (size_t)(half_index ? (p >> 1) : p) * K);
    int warp = threadIdx.x >> 5, lane = threadIdx.x & 31;
    const float* Ae = Amat + (size_t)e * R_DIM * K;
    for (int r = warp; r < R_DIM; r += 4) {
        const float4* ar = (const float4*)(Ae + (size_t)r * K);
        float s = 0.f;
        for (int i = lane; i < K / 4; i += 32) {
            float4 a = xr[i], b = ar[i];
            s += a.x * b.x + a.y * b.y + a.z * b.z + a.w * b.w;
        }
        #pragma unroll
        for (int o = 16; o; o >>= 1) s += __shfl_xor_sync(0xffffffffu, s, o);
        if (lane == 0) Tout[p * R_DIM + r] = s;
    }
}

// ---------------- fc1 epilogue: a[p,h] = silu(common[t,h] + b1[h] + scale * t1[p] . B1[e][h,:]) ----------------
__global__ void act_kernel(const float* __restrict__ B1mat, const float* __restrict__ b1) {
    int p = blockIdx.x;
    int t = p >> 1;
    int e = g_sel[p];
    __shared__ float t1s[R_DIM];
    if (threadIdx.x < R_DIM) t1s[threadIdx.x] = g_t1[p * R_DIM + threadIdx.x];
    __syncthreads();
    const float* B1e = B1mat + (size_t)e * H_DIM * R_DIM;
    for (int h = threadIdx.x; h < H_DIM; h += blockDim.x) {
        const float4* br = (const float4*)(B1e + (size_t)h * R_DIM);
        float lor = 0.f;
        #pragma unroll
        for (int q = 0; q < 4; q++) {
            float4 v = br[q];
            lor += v.x * t1s[q * 4 + 0] + v.y * t1s[q * 4 + 1]
                 + v.z * t1s[q * 4 + 2] + v.w * t1s[q * 4 + 3];
        }
        float val = g_common[(size_t)t * H_DIM + h] + b1[h] + LSCALE * lor;
        float a = val / (1.f + expf(-val));   // silu
        g_act[(size_t)p * H_DIM + h] = a;
    }
}

// ---------------- combine: out[t,d] = sum_k w_k * (base2[p,d] + b2[d] + scale * t2[p] . B2[e][d,:]) ----------------
__global__ void combine_kernel(const float* __restrict__ B2mat, const float* __restrict__ b2,
                               float* __restrict__ out) {
    int t = blockIdx.x;
    __shared__ float t2s[2][R_DIM];
    __shared__ float wsh[2];
    __shared__ int esh[2];
    if (threadIdx.x < 2 * R_DIM) t2s[threadIdx.x >> 4][threadIdx.x & 15] = g_t2[t * 2 * R_DIM + threadIdx.x];
    if (threadIdx.x < 2) { wsh[threadIdx.x] = g_wt[t * 2 + threadIdx.x]; esh[threadIdx.x] = g_sel[t * 2 + threadIdx.x]; }
    __syncthreads();
    for (int d = threadIdx.x; d < D_DIM; d += blockDim.x) {
        float val = 0.f;
        #pragma unroll
        for (int k = 0; k < 2; k++) {
            const float4* br = (const float4*)(B2mat + ((size_t)esh[k] * D_DIM + d) * R_DIM);
            float lor = 0.f;
            #pragma unroll
            for (int q = 0; q < 4; q++) {
                float4 v = br[q];
                lor += v.x * t2s[k][q * 4 + 0] + v.y * t2s[k][q * 4 + 1]
                     + v.z * t2s[k][q * 4 + 2] + v.w * t2s[k][q * 4 + 3];
            }
            val += wsh[k] * (g_base2[((size_t)t * 2 + k) * D_DIM + d] + b2[d] + LSCALE * lor);
        }
        out[(size_t)t * D_DIM + d] = val;
    }
}

// ---------------- launch ----------------
extern "C" void kernel_launch(void* const* d_in, const int* in_sizes, int n_in,
                              void* d_out, int out_size) {
    const float* x    = (const float*)d_in[0];
    const float* gate = (const float*)d_in[1];
    const float* W1   = (const float*)d_in[2];
    const float* b1   = (const float*)d_in[3];
    const float* W2   = (const float*)d_in[4];
    const float* b2   = (const float*)d_in[5];
    const float* A1   = (const float*)d_in[6];
    const float* B1   = (const float*)d_in[7];
    const float* A2   = (const float*)d_in[8];
    const float* B2   = (const float*)d_in[9];
    float* out = (float*)d_out;

    float *p_common, *p_act, *p_base2, *p_t1, *p_t2;
    cudaGetSymbolAddress((void**)&p_common, g_common);
    cudaGetSymbolAddress((void**)&p_act,    g_act);
    cudaGetSymbolAddress((void**)&p_base2,  g_base2);
    cudaGetSymbolAddress((void**)&p_t1,     g_t1);
    cudaGetSymbolAddress((void**)&p_t2,     g_t2);

    // 1. router
    router_kernel<<<N_TOK, 256>>>(x, gate);

    // 2. common_fc1 = X @ W1^T   [2048,1024] x [4096,1024]^T
    {
        dim3 grid(H_DIM / 128, N_TOK / 128);
        gemm_nt_kernel<<<grid, 256>>>(x, W1, p_common, N_TOK, H_DIM, D_DIM);
    }

    // 3. t1[p] = x[t] @ A1[e]^T
    lora_in_kernel<<<2 * N_TOK, 128>>>(x, A1, p_t1, D_DIM, 1);

    // 4. a = silu(common + b1 + scale * t1 @ B1[e]^T)
    act_kernel<<<2 * N_TOK, 256>>>(B1, b1);

    // 5. base2 = a @ W2^T   [4096,4096] x [1024,4096]^T
    {
        dim3 grid(D_DIM / 128, (2 * N_TOK) / 128);
        gemm_nt_kernel<<<grid, 256>>>(p_act, W2, p_base2, 2 * N_TOK, D_DIM, H_DIM);
    }

    // 6. t2[p] = a[p] @ A2[e]^T
    lora_in_kernel<<<2 * N_TOK, 128>>>(p_act, A2, p_t2, H_DIM, 0);

    // 7. out = sum_k w_k * (base2 + b2 + scale * t2 @ B2[e]^T)
    combine_kernel<<<N_TOK, 256>>>(B2, b2, out);
}

// round 3
// speedup vs baseline: 1.7751x; 1.7751x over previous
#include <cuda_runtime.h>
#include <math.h>

#define N_TOK 2048
#define D_DIM 1024
#define H_DIM 4096
#define E_NUM 8
#define R_DIM 16
#define LSCALE 2.0f   // lora_alpha / lora_r = 32/16

// ---------------- scratch (device globals; no allocation allowed) ----------------
__device__ float g_common[N_TOK * H_DIM];          // x @ W1^T
__device__ float g_act[N_TOK * 2 * H_DIM];         // silu(fc1) per slot
__device__ float g_base2[N_TOK * 2 * D_DIM];       // a @ W2^T per slot
__device__ float g_t1[N_TOK * 2 * R_DIM];          // x @ A1[e]^T
__device__ float g_t2[N_TOK * 2 * R_DIM];          // a @ A2[e]^T
__device__ int   g_sel[N_TOK * 2];
__device__ float g_wt[N_TOK * 2];

// ---------------- router ----------------
__global__ void router_kernel(const float* __restrict__ x, const float* __restrict__ gate) {
    int t = blockIdx.x;
    int warp = threadIdx.x >> 5, lane = threadIdx.x & 31;
    __shared__ float logits[E_NUM];
    const float4* xr = (const float4*)(x + (size_t)t * D_DIM);
    const float4* gr = (const float4*)(gate + (size_t)warp * D_DIM);
    float s = 0.f;
    for (int i = lane; i < D_DIM / 4; i += 32) {
        float4 a = xr[i], b = gr[i];
        s += a.x * b.x + a.y * b.y + a.z * b.z + a.w * b.w;
    }
    #pragma unroll
    for (int o = 16; o; o >>= 1) s += __shfl_xor_sync(0xffffffffu, s, o);
    if (lane == 0) logits[warp] = s;
    __syncthreads();
    if (threadIdx.x == 0) {
        float best = -1e30f; int i0 = 0;
        #pragma unroll
        for (int e = 0; e < E_NUM; e++) if (logits[e] > best) { best = logits[e]; i0 = e; }
        float best2 = -1e30f; int i1 = 0;
        #pragma unroll
        for (int e = 0; e < E_NUM; e++) if (e != i0 && logits[e] > best2) { best2 = logits[e]; i1 = e; }
        float p1 = expf(best2 - best);
        float inv = 1.f / (1.f + p1);
        g_sel[t * 2 + 0] = i0; g_sel[t * 2 + 1] = i1;
        g_wt[t * 2 + 0] = inv; g_wt[t * 2 + 1] = p1 * inv;
    }
}

// ---------------- tf32 tensor-core GEMM:  C[M,N] = A[M,K] @ B[N,K]^T ----------------
// 128x128 tile, BK=32, 256 threads (8 warps, 4x2), warp tile 32x64 via m16n8k8.
__device__ __forceinline__ unsigned f2tf32(float x) {
    unsigned r;
    asm("cvt.rna.tf32.f32 %0, %1;" : "=r"(r) : "f"(x));
    return r;
}

__device__ __forceinline__ void mma_tf32(float* c, const unsigned* a, const unsigned* b) {
    asm volatile(
        "mma.sync.aligned.m16n8k8.row.col.f32.tf32.tf32.f32 "
        "{%0,%1,%2,%3}, {%4,%5,%6,%7}, {%8,%9}, {%0,%1,%2,%3};"
        : "+f"(c[0]), "+f"(c[1]), "+f"(c[2]), "+f"(c[3])
        : "r"(a[0]), "r"(a[1]), "r"(a[2]), "r"(a[3]), "r"(b[0]), "r"(b[1]));
}

#define GLDS 36   // BK(32) + 4 pad: conflict-free fragment loads, float4-aligned

__global__ __launch_bounds__(256)
void gemm_tf32_kernel(const float* __restrict__ A, const float* __restrict__ B,
                      float* __restrict__ C, int M, int N, int K) {
    const int BM = 128, BN = 128, BK = 32;
    __shared__ float As[BM * GLDS];
    __shared__ float Bs[BN * GLDS];
    int bm = blockIdx.y * BM, bn = blockIdx.x * BN;
    int tid = threadIdx.x;
    int lane = tid & 31;
    int wid = tid >> 5;
    int wm = (wid >> 1) * 32;     // warp row offset (4 warps in M)
    int wn = (wid & 1) * 64;      // warp col offset (2 warps in N)
    int g = lane >> 2, tg = lane & 3;

    float acc[2][8][4];
    #pragma unroll
    for (int mt = 0; mt < 2; mt++)
        #pragma unroll
        for (int nt = 0; nt < 8; nt++)
            #pragma unroll
            for (int i = 0; i < 4; i++) acc[mt][nt][i] = 0.f;

    float4 ra[4], rb[4];

    // prologue: load K-tile 0
    #pragma unroll
    for (int l = 0; l < 4; l++) {
        int idx = tid * 4 + l;          // 0..1023
        int row = idx >> 3, q = idx & 7;
        ra[l] = *(const float4*)(A + (size_t)(bm + row) * K + q * 4);
        rb[l] = *(const float4*)(B + (size_t)(bn + row) * K + q * 4);
    }
    #pragma unroll
    for (int l = 0; l < 4; l++) {
        int idx = tid * 4 + l;
        int row = idx >> 3, q = idx & 7;
        *(float4*)&As[row * GLDS + q * 4] = ra[l];
        *(float4*)&Bs[row * GLDS + q * 4] = rb[l];
    }
    __syncthreads();

    for (int k0 = 0; k0 < K; k0 += BK) {
        bool more = (k0 + BK) < K;
        if (more) {
            #pragma unroll
            for (int l = 0; l < 4; l++) {
                int idx = tid * 4 + l;
                int row = idx >> 3, q = idx & 7;
                ra[l] = *(const float4*)(A + (size_t)(bm + row) * K + k0 + BK + q * 4);
                rb[l] = *(const float4*)(B + (size_t)(bn + row) * K + k0 + BK + q * 4);
            }
        }
        #pragma unroll
        for (int ks = 0; ks < BK; ks += 8) {
            unsigned af[2][4];
            unsigned bf[8][2];
            #pragma unroll
            for (int mt = 0; mt < 2; mt++) {
                int rbse = wm + mt * 16;
                af[mt][0] = f2tf32(As[(rbse + g) * GLDS + ks + tg]);
                af[mt][1] = f2tf32(As[(rbse + g + 8) * GLDS + ks + tg]);
                af[mt][2] = f2tf32(As[(rbse + g) * GLDS + ks + tg + 4]);
                af[mt][3] = f2tf32(As[(rbse + g + 8) * GLDS + ks + tg + 4]);
            }
            #pragma unroll
            for (int nt = 0; nt < 8; nt++) {
                int cb = wn + nt * 8;
                bf[nt][0] = f2tf32(Bs[(cb + g) * GLDS + ks + tg]);
                bf[nt][1] = f2tf32(Bs[(cb + g) * GLDS + ks + tg + 4]);
            }
            #pragma unroll
            for (int mt = 0; mt < 2; mt++)
                #pragma unroll
                for (int nt = 0; nt < 8; nt++)
                    mma_tf32(acc[mt][nt], af[mt], bf[nt]);
        }
        __syncthreads();
        if (more) {
            #pragma unroll
            for (int l = 0; l < 4; l++) {
                int idx = tid * 4 + l;
                int row = idx >> 3, q = idx & 7;
                *(float4*)&As[row * GLDS + q * 4] = ra[l];
                *(float4*)&Bs[row * GLDS + q * 4] = rb[l];
            }
            __syncthreads();
        }
    }

    // epilogue: direct fp32 stores
    #pragma unroll
    for (int mt = 0; mt < 2; mt++) {
        #pragma unroll
        for (int nt = 0; nt < 8; nt++) {
            int r0 = bm + wm + mt * 16 + g;
            int c0 = bn + wn + nt * 8 + 2 * tg;
            C[(size_t)r0 * N + c0]           = acc[mt][nt][0];
            C[(size_t)r0 * N + c0 + 1]       = acc[mt][nt][1];
            C[(size_t)(r0 + 8) * N + c0]     = acc[mt][nt][2];
            C[(size_t)(r0 + 8) * N + c0 + 1] = acc[mt][nt][3];
        }
    }
}

// ---------------- rank-16 down-projection ----------------
__global__ void lora_in_kernel(const float* __restrict__ X, const float* __restrict__ Amat,
                               float* __restrict__ Tout, int K, int half_index) {
    int p = blockIdx.x;
    int e = g_sel[p];
    const float4* xr = (const float4*)(X + (size_t)(half_index ? (p >> 1) : p) * K);
    int warp = threadIdx.x >> 5, lane = threadIdx.x & 31;
    const float* Ae = Amat + (size_t)e * R_DIM * K;
    for (int r = warp; r < R_DIM; r += 4) {
        const float4* ar = (const float4*)(Ae + (size_t)r * K);
        float s = 0.f;
        for (int i = lane; i < K / 4; i += 32) {
            float4 a = xr[i], b = ar[i];
            s += a.x * b.x + a.y * b.y + a.z * b.z + a.w * b.w;
        }
        #pragma unroll
        for (int o = 16; o; o >>= 1) s += __shfl_xor_sync(0xffffffffu, s, o);
        if (lane == 0) Tout[p * R_DIM + r] = s;
    }
}

// ---------------- fc1 epilogue ----------------
__global__ void act_kernel(const float* __restrict__ B1mat, const float* __restrict__ b1) {
    int p = blockIdx.x;
    int t = p >> 1;
    int e = g_sel[p];
    __shared__ float t1s[R_DIM];
    if (threadIdx.x < R_DIM) t1s[threadIdx.x] = g_t1[p * R_DIM + threadIdx.x];
    __syncthreads();
    const float* B1e = B1mat + (size_t)e * H_DIM * R_DIM;
    for (int h = threadIdx.x; h < H_DIM; h += blockDim.x) {
        const float4* br = (const float4*)(B1e + (size_t)h * R_DIM);
        float lor = 0.f;
        #pragma unroll
        for (int q = 0; q < 4; q++) {
            float4 v = br[q];
            lor += v.x * t1s[q * 4 + 0] + v.y * t1s[q * 4 + 1]
                 + v.z * t1s[q * 4 + 2] + v.w * t1s[q * 4 + 3];
        }
        float val = g_common[(size_t)t * H_DIM + h] + b1[h] + LSCALE * lor;
        float a = val / (1.f + expf(-val));   // silu
        g_act[(size_t)p * H_DIM + h] = a;
    }
}

// ---------------- combine ----------------
__global__ void combine_kernel(const float* __restrict__ B2mat, const float* __restrict__ b2,
                               float* __restrict__ out) {
    int t = blockIdx.x;
    __shared__ float t2s[2][R_DIM];
    __shared__ float wsh[2];
    __shared__ int esh[2];
    if (threadIdx.x < 2 * R_DIM) t2s[threadIdx.x >> 4][threadIdx.x & 15] = g_t2[t * 2 * R_DIM + threadIdx.x];
    if (threadIdx.x < 2) { wsh[threadIdx.x] = g_wt[t * 2 + threadIdx.x]; esh[threadIdx.x] = g_sel[t * 2 + threadIdx.x]; }
    __syncthreads();
    for (int d = threadIdx.x; d < D_DIM; d += blockDim.x) {
        float val = 0.f;
        #pragma unroll
        for (int k = 0; k < 2; k++) {
            const float4* br = (const float4*)(B2mat + ((size_t)esh[k] * D_DIM + d) * R_DIM);
            float lor = 0.f;
            #pragma unroll
            for (int q = 0; q < 4; q++) {
                float4 v = br[q];
                lor += v.x * t2s[k][q * 4 + 0] + v.y * t2s[k][q * 4 + 1]
                     + v.z * t2s[k][q * 4 + 2] + v.w * t2s[k][q * 4 + 3];
            }
            val += wsh[k] * (g_base2[((size_t)t * 2 + k) * D_DIM + d] + b2[d] + LSCALE * lor);
        }
        out[(size_t)t * D_DIM + d] = val;
    }
}

// ---------------- launch ----------------
extern "C" void kernel_launch(void* const* d_in, const int* in_sizes, int n_in,
                              void* d_out, int out_size) {
    const float* x    = (const float*)d_in[0];
    const float* gate = (const float*)d_in[1];
    const float* W1   = (const float*)d_in[2];
    const float* b1   = (const float*)d_in[3];
    const float* W2   = (const float*)d_in[4];
    const float* b2   = (const float*)d_in[5];
    const float* A1   = (const float*)d_in[6];
    const float* B1   = (const float*)d_in[7];
    const float* A2   = (const float*)d_in[8];
    const float* B2   = (const float*)d_in[9];
    float* out = (float*)d_out;

    float *p_common, *p_act, *p_base2, *p_t1, *p_t2;
    cudaGetSymbolAddress((void**)&p_common, g_common);
    cudaGetSymbolAddress((void**)&p_act,    g_act);
    cudaGetSymbolAddress((void**)&p_base2,  g_base2);
    cudaGetSymbolAddress((void**)&p_t1,     g_t1);
    cudaGetSymbolAddress((void**)&p_t2,     g_t2);

    // 1. router
    router_kernel<<<N_TOK, 256>>>(x, gate);

    // 2. common_fc1 = X @ W1^T   [2048,1024] x [4096,1024]^T
    {
        dim3 grid(H_DIM / 128, N_TOK / 128);
        gemm_tf32_kernel<<<grid, 256>>>(x, W1, p_common, N_TOK, H_DIM, D_DIM);
    }

    // 3. t1[p] = x[t] @ A1[e]^T
    lora_in_kernel<<<2 * N_TOK, 128>>>(x, A1, p_t1, D_DIM, 1);

    // 4. a = silu(common + b1 + scale * t1 @ B1[e]^T)
    act_kernel<<<2 * N_TOK, 256>>>(B1, b1);

    // 5. base2 = a @ W2^T   [4096,4096] x [1024,4096]^T
    {
        dim3 grid(D_DIM / 128, (2 * N_TOK) / 128);
        gemm_tf32_kernel<<<grid, 256>>>(p_act, W2, p_base2, 2 * N_TOK, D_DIM, H_DIM);
    }

    // 6. t2[p] = a[p] @ A2[e]^T
    lora_in_kernel<<<2 * N_TOK, 128>>>(p_act, A2, p_t2, H_DIM, 0);

    // 7. out = sum_k w_k * (base2 + b2 + scale * t2 @ B2[e]^T)
    combine_kernel<<<N_TOK, 256>>>(B2, b2, out);
}